// round 9
// baseline (speedup 1.0000x reference)
#include <cuda_runtime.h>
#include <math.h>
#include <stdint.h>

#define Hc   1024
#define Nst  64
#define Lt   4096
#define OUTc 512
#define BSz  2
#define BC   (BSz*Hc)
#define CH3  342   // per-axis posenc channels
#define Tch  64    // chunk length
#define NCHK 64    // Lt / Tch

// ---------------- helpers ----------------
__device__ __forceinline__ float tf32rna(float v) {
    uint32_t u; asm("cvt.rna.tf32.f32 %0, %1;" : "=r"(u) : "f"(v));
    return __uint_as_float(u);
}
__device__ __forceinline__ float gelu_f(float s) {
    float a2 = 1.5957691216057308f * fmaf(0.044715f * s, s * s, s);
    float e  = __expf(a2);
    float th = 1.0f - __fdividef(2.0f, e + 1.0f);
    return 0.5f * s * (1.0f + th);
}

// ---------------- scratch ----------------
__device__ float g_vt[BC*Lt];        // v transposed per (b,c): [bc][j][k] 64x64, tf32-rounded
__device__ float g_yT[BC*Lt];        // gelu output, (b, c, l), tf32-rounded
__device__ float g_Wt[Hc*OUTc];      // W pre-rounded to tf32
__device__ float g_Qt[Hc*64*128];    // [c][j][n]   A-operand of pass A  (tf32)
__device__ float g_GT[Hc*192*64];    // [c][r][t]   A-operand of pass C  (tf32)
__device__ float g_B [BC*128*64];    // [bc][n][k]  chunk contributions
__device__ float g_S0[BC*128*64];    // [bc][n][k]  chunk start states (tf32)
__device__ float g_wre[Hc*Nst],  g_wim[Hc*Nst];
__device__ float g_wTre[Hc*Nst], g_wTim[Hc*Nst];   // w^Tch
__device__ float g_ctre[Hc*Nst], g_ctim[Hc*Nst];
__device__ float g_emb[3*16*CH3];

// ---------------- posenc tables ----------------
__global__ void prep_emb_kernel() {
    int idx = blockIdx.x * blockDim.x + threadIdx.x;
    if (idx >= 3*16*CH3) return;
    int k   = idx % CH3;
    int pos = (idx / CH3) % 16;
    int i   = k >> 1;
    float freq = expf(-logf(10000.0f) * (float)(2*i) / (float)CH3);
    float arg  = (float)pos * freq;
    g_emb[idx] = (k & 1) ? cosf(arg) : sinf(arg);
}

// ---------------- W -> tf32 ----------------
__global__ void prep_wt_kernel(const float* __restrict__ W) {
    int i4 = blockIdx.x * blockDim.x + threadIdx.x;
    if (i4 >= Hc*OUTc/4) return;
    float4 w = ((const float4*)W)[i4];
    ((float4*)g_Wt)[i4] = make_float4(tf32rna(w.x), tf32rna(w.y), tf32rna(w.z), tf32rna(w.w));
}

// ---------------- discretize (fp64 for w^Tch) ----------------
__global__ void prep_ct_kernel(const float* __restrict__ log_dt,
                               const float* __restrict__ Are, const float* __restrict__ Aim,
                               const float* __restrict__ Cre, const float* __restrict__ Cim) {
    int idx = blockIdx.x * blockDim.x + threadIdx.x;
    if (idx >= Hc*Nst) return;
    int c = idx >> 6;
    double dt  = exp((double)log_dt[c]);
    double ar  = (double)Are[idx], ai = (double)Aim[idx];
    double dar = dt*ar, dai = dt*ai;
    double er  = exp(dar);
    double wr = er*cos(dai), wi = er*sin(dai);
    g_wre[idx] = (float)wr; g_wim[idx] = (float)wi;
    double erT = exp((double)Tch * dar);
    g_wTre[idx] = (float)(erT*cos((double)Tch*dai));
    g_wTim[idx] = (float)(erT*sin((double)Tch*dai));
    double nr = wr - 1.0, ni = wi;
    double inv = 1.0 / (ar*ar + ai*ai);
    double qr = (nr*ar + ni*ai) * inv;
    double qi = (ni*ar - nr*ai) * inv;
    double cr = (double)Cre[idx], ci = (double)Cim[idx];
    g_ctre[idx] = (float)(2.0*(cr*qr - ci*qi));
    g_ctim[idx] = (float)(2.0*(cr*qi + ci*qr));
}

// ---------------- build Qt / GT (+ Toeplitz with D on diagonal) per channel ----------------
__global__ __launch_bounds__(64) void build_kernel(const float* __restrict__ D) {
    __shared__ float smre[64][65];
    __shared__ float smim[64][65];
    __shared__ float kv[64];
    int c = blockIdx.x;
    int n = threadIdx.x;          // state index 0..63
    int nn = c*64 + n;
    float wr = g_wre[nn], wi = g_wim[nn];
    float cr = g_ctre[nn], ci = g_ctim[nn];
    float* Qt = g_Qt + (size_t)c * 64*128;
    float* GT = g_GT + (size_t)c * 192*64;

    // phase 1: powers w^0..w^63  -> Qt[j][2n] = Re(w^{63-j}), [2n+1] = Im
    {
        float pr = 1.f, pi = 0.f;
        for (int d = 0; d < 64; ++d) {
            smre[d][n] = pr; smim[d][n] = pi;
            float t = pr*wr - pi*wi; pi = pr*wi + pi*wr; pr = t;
        }
    }
    __syncthreads();
    for (int j = 0; j < 64; ++j) {
        float2 q = make_float2(tf32rna(smre[63-j][n]), tf32rna(smim[63-j][n]));
        *(float2*)&Qt[j*128 + 2*n] = q;
    }
    __syncthreads();
    // phase 2: z = Ct*w^{t+1}  -> GT[2n][t]=Re z, GT[2n+1][t]=-Im z
    {
        float zr = cr*wr - ci*wi, zi = cr*wi + ci*wr;
        for (int t = 0; t < 64; ++t) {
            smre[t][n] = zr; smim[t][n] = -zi;
            float tt = zr*wr - zi*wi; zi = zr*wi + zi*wr; zr = tt;
        }
    }
    __syncthreads();
    for (int r = 0; r < 128; ++r) {
        int sn = r >> 1;
        GT[r*64 + n] = tf32rna((r & 1) ? smim[n][sn] : smre[n][sn]);
    }
    __syncthreads();
    // phase 3: K[d] = Re(sum_n Ct*w^d); TT rows 128+j: K[t-j], diag += D
    {
        float zr = cr, zi = ci;
        for (int d = 0; d < 64; ++d) {
            smre[d][n] = zr;
            float tt = zr*wr - zi*wi; zi = zr*wi + zi*wr; zr = tt;
        }
    }
    __syncthreads();
    {
        float s = 0.f;
        for (int q = 0; q < 64; ++q) s += smre[n][q];
        kv[n] = s;
    }
    __syncthreads();
    float dc = D[c];
    for (int j = 0; j < 64; ++j) {
        float val = (n >= j) ? kv[n - j] : 0.f;
        if (n == j) val += dc;
        GT[(128 + j)*64 + n] = tf32rna(val);
    }
}

// ---------------- v = x + posenc, transposed store [bc][j][k] ----------------
__global__ void v_kernel(const float* __restrict__ x) {
    int i4 = blockIdx.x * blockDim.x + threadIdx.x;
    if (i4 >= BC*Lt/4) return;
    int l4 = i4 & (Lt/4 - 1);
    int bc = i4 >> 10;
    int c  = bc & (Hc - 1);
    int l  = l4 << 2;
    int lw = l & 15, lh = (l >> 4) & 15, lf = l >> 8;
    float4 xv = ((const float4*)x)[i4];
    float4 pv;
    if (c < CH3) {
        float e = g_emb[lf*CH3 + c];
        pv = make_float4(e, e, e, e);
    } else if (c < 2*CH3) {
        float e = g_emb[(16 + lh)*CH3 + (c - CH3)];
        pv = make_float4(e, e, e, e);
    } else {
        int k = c - 2*CH3;
        const float* ez = g_emb + 32*CH3 + k;
        pv = make_float4(ez[(lw+0)*CH3], ez[(lw+1)*CH3], ez[(lw+2)*CH3], ez[(lw+3)*CH3]);
    }
    int kk = l >> 6, j = l & 63;           // l = kk*64 + j, j multiple of 4
    float* dst = g_vt + (size_t)bc * Lt + (size_t)j * 64 + kk;
    dst[0]   = tf32rna(xv.x + pv.x);
    dst[64]  = tf32rna(xv.y + pv.y);
    dst[128] = tf32rna(xv.z + pv.z);
    dst[192] = tf32rna(xv.w + pv.w);
}

// ---------------- pass A (GEMM): B[n][k] = Qt^T @ V ----------------
// per CTA = (b,c): M=128(n) N=64(k) K=64(j); 128 threads = 4 warps (32 M-rows each)
__global__ __launch_bounds__(128) void gemmA_kernel() {
    __shared__ float As[32][132];
    __shared__ float vs[64][68];
    int bc = blockIdx.x;
    int c  = bc & (Hc - 1);
    int t  = threadIdx.x;
    int lane = t & 31, wrp = t >> 5;
    int gID = lane >> 2, tig = lane & 3;
    int om = wrp << 5;

    const float* Qt = g_Qt + (size_t)c * 64*128;
    const float* vt = g_vt + (size_t)bc * Lt;

    // load V (64x64) into vs
    #pragma unroll
    for (int p = 0; p < 8; ++p) {
        int idx = (t + p*128) * 4;
        int r = idx >> 6, col = idx & 63;
        *(float4*)&vs[r][col] = *(const float4*)&vt[idx];
    }

    float acc[2][8][4];
    #pragma unroll
    for (int mt = 0; mt < 2; ++mt)
        #pragma unroll
        for (int nt = 0; nt < 8; ++nt)
            #pragma unroll
            for (int r = 0; r < 4; ++r) acc[mt][nt][r] = 0.f;

    #pragma unroll
    for (int s = 0; s < 2; ++s) {
        __syncthreads();
        #pragma unroll
        for (int p = 0; p < 8; ++p) {
            int idx = (t + p*128) * 4;
            int r = idx >> 7, col = idx & 127;
            *(float4*)&As[r][col] = *(const float4*)&Qt[s*32*128 + idx];
        }
        __syncthreads();
        #pragma unroll
        for (int k8 = 0; k8 < 4; ++k8) {
            int kd = k8 << 3;
            uint32_t a[2][4];
            #pragma unroll
            for (int mt = 0; mt < 2; ++mt) {
                int r0 = om + (mt << 4) + gID;
                a[mt][0] = __float_as_uint(As[kd + tig    ][r0]);
                a[mt][1] = __float_as_uint(As[kd + tig    ][r0 + 8]);
                a[mt][2] = __float_as_uint(As[kd + tig + 4][r0]);
                a[mt][3] = __float_as_uint(As[kd + tig + 4][r0 + 8]);
            }
            uint32_t bf[8][2];
            #pragma unroll
            for (int nt = 0; nt < 8; ++nt) {
                int cn = (nt << 3) + gID;
                bf[nt][0] = __float_as_uint(vs[(s<<5) + kd + tig    ][cn]);
                bf[nt][1] = __float_as_uint(vs[(s<<5) + kd + tig + 4][cn]);
            }
            #pragma unroll
            for (int mt = 0; mt < 2; ++mt)
                #pragma unroll
                for (int nt = 0; nt < 8; ++nt) {
                    asm("mma.sync.aligned.m16n8k8.row.col.f32.tf32.tf32.f32 "
                        "{%0,%1,%2,%3},{%4,%5,%6,%7},{%8,%9},{%0,%1,%2,%3};"
                        : "+f"(acc[mt][nt][0]), "+f"(acc[mt][nt][1]),
                          "+f"(acc[mt][nt][2]), "+f"(acc[mt][nt][3])
                        : "r"(a[mt][0]), "r"(a[mt][1]), "r"(a[mt][2]), "r"(a[mt][3]),
                          "r"(bf[nt][0]), "r"(bf[nt][1]));
                }
        }
    }
    float* Bp = g_B + (size_t)bc * 128*64;
    #pragma unroll
    for (int mt = 0; mt < 2; ++mt) {
        int n0 = om + (mt << 4) + gID;
        #pragma unroll
        for (int nt = 0; nt < 8; ++nt) {
            int k0 = (nt << 3) + (tig << 1);
            *(float2*)&Bp[(size_t)n0      * 64 + k0] = make_float2(acc[mt][nt][0], acc[mt][nt][1]);
            *(float2*)&Bp[(size_t)(n0+8)  * 64 + k0] = make_float2(acc[mt][nt][2], acc[mt][nt][3]);
        }
    }
}

// ---------------- scan: S0(k+1) = w^64 * S0(k) + B(k) ----------------
__global__ __launch_bounds__(128) void scan_kernel() {
    int bc   = blockIdx.x * 4 + (threadIdx.x >> 5);
    int lane = threadIdx.x & 31;
    int c    = bc & (Hc - 1);
    int n0   = c*64 + lane, n1 = n0 + 32;
    float wra = g_wTre[n0], wia = g_wTim[n0];
    float wrb = g_wTre[n1], wib = g_wTim[n1];

    const float* Bp = g_B  + (size_t)bc * 128*64;
    float*       Sp = g_S0 + (size_t)bc * 128*64;
    int ra = 2*lane, rb = 2*lane + 64;

    float sra = 0.f, sia = 0.f, srb = 0.f, sib = 0.f;
    #pragma unroll 4
    for (int k = 0; k < 64; ++k) {
        Sp[(ra  )*64 + k] = tf32rna(sra);
        Sp[(ra+1)*64 + k] = tf32rna(sia);
        Sp[(rb  )*64 + k] = tf32rna(srb);
        Sp[(rb+1)*64 + k] = tf32rna(sib);
        float bra = Bp[(ra  )*64 + k];
        float bia = Bp[(ra+1)*64 + k];
        float brb = Bp[(rb  )*64 + k];
        float bib = Bp[(rb+1)*64 + k];
        float nra = fmaf(wra, sra, fmaf(-wia, sia, bra));
        sia       = fmaf(wra, sia, fmaf( wia, sra, bia));
        sra = nra;
        float nrb = fmaf(wrb, srb, fmaf(-wib, sib, brb));
        sib       = fmaf(wrb, sib, fmaf( wib, srb, bib));
        srb = nrb;
    }
}

// ---------------- pass C (GEMM): Y = [G|T] @ [S0;V], fused gelu ----------------
// per CTA = (b,c): M=64(t) N=64(k) K=192; 128 threads = 4 warps (16 M-rows each)
__global__ __launch_bounds__(128) void gemmC_kernel() {
    __shared__ float As[64][68];
    __shared__ float Bs[64][68];
    int bc = blockIdx.x;
    int c  = bc & (Hc - 1);
    int t  = threadIdx.x;
    int lane = t & 31, wrp = t >> 5;
    int gID = lane >> 2, tig = lane & 3;
    int om = wrp << 4;

    const float* GT = g_GT + (size_t)c * 192*64;
    const float* Sp = g_S0 + (size_t)bc * 128*64;
    const float* vt = g_vt + (size_t)bc * Lt;

    float acc[8][4];
    #pragma unroll
    for (int nt = 0; nt < 8; ++nt)
        #pragma unroll
        for (int r = 0; r < 4; ++r) acc[nt][r] = 0.f;

    #pragma unroll
    for (int s = 0; s < 3; ++s) {
        __syncthreads();
        const float* bsrc = (s < 2) ? (Sp + (size_t)s*64*64) : vt;
        #pragma unroll
        for (int p = 0; p < 8; ++p) {
            int idx = (t + p*128) * 4;
            int r = idx >> 6, col = idx & 63;
            *(float4*)&As[r][col] = *(const float4*)&GT[s*64*64 + idx];
            *(float4*)&Bs[r][col] = *(const float4*)&bsrc[idx];
        }
        __syncthreads();
        #pragma unroll
        for (int k8 = 0; k8 < 8; ++k8) {
            int kd = k8 << 3;
            uint32_t a[4];
            int r0 = om + gID;
            a[0] = __float_as_uint(As[kd + tig    ][r0]);
            a[1] = __float_as_uint(As[kd + tig    ][r0 + 8]);
            a[2] = __float_as_uint(As[kd + tig + 4][r0]);
            a[3] = __float_as_uint(As[kd + tig + 4][r0 + 8]);
            #pragma unroll
            for (int nt = 0; nt < 8; ++nt) {
                int cn = (nt << 3) + gID;
                uint32_t b0 = __float_as_uint(Bs[kd + tig    ][cn]);
                uint32_t b1 = __float_as_uint(Bs[kd + tig + 4][cn]);
                asm("mma.sync.aligned.m16n8k8.row.col.f32.tf32.tf32.f32 "
                    "{%0,%1,%2,%3},{%4,%5,%6,%7},{%8,%9},{%0,%1,%2,%3};"
                    : "+f"(acc[nt][0]), "+f"(acc[nt][1]),
                      "+f"(acc[nt][2]), "+f"(acc[nt][3])
                    : "r"(a[0]), "r"(a[1]), "r"(a[2]), "r"(a[3]),
                      "r"(b0), "r"(b1));
            }
        }
    }
    // epilogue: y at (trow, kcol) -> l = k*64 + t; gelu; tf32 round
    float* yp = g_yT + (size_t)bc * Lt;
    int t0 = om + gID;
    #pragma unroll
    for (int nt = 0; nt < 8; ++nt) {
        int k0 = (nt << 3) + (tig << 1);
        yp[(size_t)k0    *64 + t0    ] = tf32rna(gelu_f(acc[nt][0]));
        yp[(size_t)(k0+1)*64 + t0    ] = tf32rna(gelu_f(acc[nt][1]));
        yp[(size_t)k0    *64 + t0 + 8] = tf32rna(gelu_f(acc[nt][2]));
        yp[(size_t)(k0+1)*64 + t0 + 8] = tf32rna(gelu_f(acc[nt][3]));
    }
}

// ---------------- final tf32 GEMM: out = Wt^T @ yT + bias ----------------
// tile 128(o) x 128(l), BK=16, 256 threads = 8 warps
__global__ __launch_bounds__(256) void gemm_kernel(const float* __restrict__ bias,
                                                   float* __restrict__ out) {
    __shared__ float Ws[2][16][132];
    __shared__ float Ys[2][16][132];
    int b  = blockIdx.z;
    int oo = blockIdx.y << 7;
    int ll = blockIdx.x << 7;
    int t  = threadIdx.x;
    int lane = t & 31, wid = t >> 5;
    int om = (wid & 3) << 5;
    int on = (wid >> 2) << 6;
    int gID = lane >> 2, tig = lane & 3;

    int lr = t >> 4;
    int lc = (t & 15) << 2;
    const float* Wp = g_Wt + (size_t)lr * OUTc + oo + lc;
    const float* Yp = g_yT + ((size_t)b * Hc + lr) * Lt + ll + lc;

    float4 wv0 = *(const float4*)Wp;
    float4 wv1 = *(const float4*)(Wp + 64);
    float4 yv0 = *(const float4*)Yp;
    float4 yv1 = *(const float4*)(Yp + 64);

    float acc[2][8][4];
    #pragma unroll
    for (int mt = 0; mt < 2; ++mt)
        #pragma unroll
        for (int nt = 0; nt < 8; ++nt)
            #pragma unroll
            for (int r = 0; r < 4; ++r) acc[mt][nt][r] = 0.f;

    int buf = 0;
    for (int s = 0; s < Hc/16; ++s) {
        *(float4*)&Ws[buf][lr][lc]      = wv0;
        *(float4*)&Ws[buf][lr][lc + 64] = wv1;
        *(float4*)&Ys[buf][lr][lc]      = yv0;
        *(float4*)&Ys[buf][lr][lc + 64] = yv1;
        __syncthreads();
        if (s + 1 < Hc/16) {
            size_t ko = (size_t)(s + 1) * 16;
            wv0 = *(const float4*)(Wp + ko * OUTc);
            wv1 = *(const float4*)(Wp + ko * OUTc + 64);
            yv0 = *(const float4*)(Yp + ko * Lt);
            yv1 = *(const float4*)(Yp + ko * Lt + 64);
        }
        #pragma unroll
        for (int k8 = 0; k8 < 16; k8 += 8) {
            uint32_t a[2][4];
            #pragma unroll
            for (int mt = 0; mt < 2; ++mt) {
                int r0 = om + (mt << 4) + gID;
                a[mt][0] = __float_as_uint(Ws[buf][k8 + tig    ][r0]);
                a[mt][1] = __float_as_uint(Ws[buf][k8 + tig    ][r0 + 8]);
                a[mt][2] = __float_as_uint(Ws[buf][k8 + tig + 4][r0]);
                a[mt][3] = __float_as_uint(Ws[buf][k8 + tig + 4][r0 + 8]);
            }
            uint32_t bf[8][2];
            #pragma unroll
            for (int nt = 0; nt < 8; ++nt) {
                int cn = on + (nt << 3) + gID;
                bf[nt][0] = __float_as_uint(Ys[buf][k8 + tig    ][cn]);
                bf[nt][1] = __float_as_uint(Ys[buf][k8 + tig + 4][cn]);
            }
            #pragma unroll
            for (int mt = 0; mt < 2; ++mt)
                #pragma unroll
                for (int nt = 0; nt < 8; ++nt) {
                    asm("mma.sync.aligned.m16n8k8.row.col.f32.tf32.tf32.f32 "
                        "{%0,%1,%2,%3},{%4,%5,%6,%7},{%8,%9},{%0,%1,%2,%3};"
                        : "+f"(acc[mt][nt][0]), "+f"(acc[mt][nt][1]),
                          "+f"(acc[mt][nt][2]), "+f"(acc[mt][nt][3])
                        : "r"(a[mt][0]), "r"(a[mt][1]), "r"(a[mt][2]), "r"(a[mt][3]),
                          "r"(bf[nt][0]), "r"(bf[nt][1]));
                }
        }
        buf ^= 1;
    }

    #pragma unroll
    for (int mt = 0; mt < 2; ++mt) {
        int o0 = oo + om + (mt << 4) + gID;
        float b0 = __ldg(&bias[o0]);
        float b8 = __ldg(&bias[o0 + 8]);
        float* r0p = out + ((size_t)b * OUTc + o0)     * Lt + ll + on + (tig << 1);
        float* r8p = out + ((size_t)b * OUTc + o0 + 8) * Lt + ll + on + (tig << 1);
        #pragma unroll
        for (int nt = 0; nt < 8; ++nt) {
            *(float2*)(r0p + (nt << 3)) = make_float2(acc[mt][nt][0] + b0, acc[mt][nt][1] + b0);
            *(float2*)(r8p + (nt << 3)) = make_float2(acc[mt][nt][2] + b8, acc[mt][nt][3] + b8);
        }
    }
}

// ---------------- launch ----------------
extern "C" void kernel_launch(void* const* d_in, const int* in_sizes, int n_in,
                              void* d_out, int out_size) {
    const float* x      = (const float*)d_in[0];
    const float* log_dt = (const float*)d_in[1];
    const float* A_re   = (const float*)d_in[2];
    const float* A_im   = (const float*)d_in[3];
    const float* C_re   = (const float*)d_in[4];
    const float* C_im   = (const float*)d_in[5];
    const float* D      = (const float*)d_in[6];
    const float* W      = (const float*)d_in[7];
    const float* bias   = (const float*)d_in[8];
    float* out = (float*)d_out;

    prep_emb_kernel<<<(3*16*CH3 + 255)/256, 256>>>();
    prep_ct_kernel<<<(Hc*Nst + 255)/256, 256>>>(log_dt, A_re, A_im, C_re, C_im);
    prep_wt_kernel<<<(Hc*OUTc/4 + 255)/256, 256>>>(W);
    build_kernel<<<Hc, 64>>>(D);
    v_kernel<<<(BC*Lt/4 + 255)/256, 256>>>(x);
    gemmA_kernel<<<BC, 128>>>();
    scan_kernel<<<BC/4, 128>>>();
    gemmC_kernel<<<BC, 128>>>();
    gemm_kernel<<<dim3(Lt/128, OUTc/128, BSz), 256>>>(bias, out);
}

// round 10
// speedup vs baseline: 1.6592x; 1.6592x over previous
#include <cuda_runtime.h>
#include <math.h>
#include <stdint.h>

#define Hc   1024
#define Nst  64
#define Lt   4096
#define OUTc 512
#define BSz  2
#define BC   (BSz*Hc)
#define CH3  342   // per-axis posenc channels

// ---------------- helpers ----------------
__device__ __forceinline__ float tf32rna(float v) {
    uint32_t u; asm("cvt.rna.tf32.f32 %0, %1;" : "=r"(u) : "f"(v));
    return __uint_as_float(u);
}
__device__ __forceinline__ float gelu_f(float s) {
    float a2 = 1.5957691216057308f * fmaf(0.044715f * s, s * s, s);
    float e  = __expf(a2);
    float th = 1.0f - __fdividef(2.0f, e + 1.0f);
    return 0.5f * s * (1.0f + th);
}

// ---------------- scratch ----------------
__device__ float g_vt[BC*Lt];        // v transposed per (b,c): [bc][j][k] 64x64, tf32
__device__ float g_yT[BC*Lt];        // gelu output, (b, c, l), tf32
__device__ float g_Wt[Hc*OUTc];      // W tf32
__device__ float g_Qt[Hc*64*128];    // [c][j][n]  pass-A A-operand (tf32)
__device__ float g_GT[Hc*192*64];    // [c][r][t]  pass-C A-operand (tf32)
__device__ float g_wre[Hc*Nst],  g_wim[Hc*Nst];
__device__ float g_wTre[Hc*Nst], g_wTim[Hc*Nst];   // w^64
__device__ float g_ctre[Hc*Nst], g_ctim[Hc*Nst];
__device__ float g_emb[3*16*CH3];

// ---------------- posenc tables ----------------
__global__ void prep_emb_kernel() {
    int idx = blockIdx.x * blockDim.x + threadIdx.x;
    if (idx >= 3*16*CH3) return;
    int k   = idx % CH3;
    int pos = (idx / CH3) % 16;
    int i   = k >> 1;
    float freq = expf(-logf(10000.0f) * (float)(2*i) / (float)CH3);
    float arg  = (float)pos * freq;
    g_emb[idx] = (k & 1) ? cosf(arg) : sinf(arg);
}

// ---------------- W -> tf32 ----------------
__global__ void prep_wt_kernel(const float* __restrict__ W) {
    int i4 = blockIdx.x * blockDim.x + threadIdx.x;
    if (i4 >= Hc*OUTc/4) return;
    float4 w = ((const float4*)W)[i4];
    ((float4*)g_Wt)[i4] = make_float4(tf32rna(w.x), tf32rna(w.y), tf32rna(w.z), tf32rna(w.w));
}

// ---------------- discretize (fp64 for w^64) ----------------
__global__ void prep_ct_kernel(const float* __restrict__ log_dt,
                               const float* __restrict__ Are, const float* __restrict__ Aim,
                               const float* __restrict__ Cre, const float* __restrict__ Cim) {
    int idx = blockIdx.x * blockDim.x + threadIdx.x;
    if (idx >= Hc*Nst) return;
    int c = idx >> 6;
    double dt  = exp((double)log_dt[c]);
    double ar  = (double)Are[idx], ai = (double)Aim[idx];
    double dar = dt*ar, dai = dt*ai;
    double er  = exp(dar);
    double wr = er*cos(dai), wi = er*sin(dai);
    g_wre[idx] = (float)wr; g_wim[idx] = (float)wi;
    double erT = exp(64.0 * dar);
    g_wTre[idx] = (float)(erT*cos(64.0*dai));
    g_wTim[idx] = (float)(erT*sin(64.0*dai));
    double nr = wr - 1.0, ni = wi;
    double inv = 1.0 / (ar*ar + ai*ai);
    double qr = (nr*ar + ni*ai) * inv;
    double qi = (ni*ar - nr*ai) * inv;
    double cr = (double)Cre[idx], ci = (double)Cim[idx];
    g_ctre[idx] = (float)(2.0*(cr*qr - ci*qi));
    g_ctim[idx] = (float)(2.0*(cr*qi + ci*qr));
}

// ---------------- build Qt / GT (+ Toeplitz with D on diagonal) per channel ----------------
__global__ __launch_bounds__(64) void build_kernel(const float* __restrict__ D) {
    __shared__ float smre[64][65];
    __shared__ float smim[64][65];
    __shared__ float kv[64];
    int c = blockIdx.x;
    int n = threadIdx.x;
    int nn = c*64 + n;
    float wr = g_wre[nn], wi = g_wim[nn];
    float cr = g_ctre[nn], ci = g_ctim[nn];
    float* Qt = g_Qt + (size_t)c * 64*128;
    float* GT = g_GT + (size_t)c * 192*64;

    // powers w^0..w^63 -> Qt[j][2n]=Re(w^{63-j}), [2n+1]=Im
    {
        float pr = 1.f, pi = 0.f;
        for (int d = 0; d < 64; ++d) {
            smre[d][n] = pr; smim[d][n] = pi;
            float t = pr*wr - pi*wi; pi = pr*wi + pi*wr; pr = t;
        }
    }
    __syncthreads();
    for (int j = 0; j < 64; ++j) {
        float2 q = make_float2(tf32rna(smre[63-j][n]), tf32rna(smim[63-j][n]));
        *(float2*)&Qt[j*128 + 2*n] = q;
    }
    __syncthreads();
    // z = Ct*w^{t+1} -> GT[2n][t]=Re z, GT[2n+1][t]=-Im z
    {
        float zr = cr*wr - ci*wi, zi = cr*wi + ci*wr;
        for (int t = 0; t < 64; ++t) {
            smre[t][n] = zr; smim[t][n] = -zi;
            float tt = zr*wr - zi*wi; zi = zr*wi + zi*wr; zr = tt;
        }
    }
    __syncthreads();
    for (int r = 0; r < 128; ++r) {
        int sn = r >> 1;
        GT[r*64 + n] = tf32rna((r & 1) ? smim[n][sn] : smre[n][sn]);
    }
    __syncthreads();
    // K[d] = Re(sum_n Ct*w^d); Toeplitz rows 128+j: K[t-j], diag += D
    {
        float zr = cr, zi = ci;
        for (int d = 0; d < 64; ++d) {
            smre[d][n] = zr;
            float tt = zr*wr - zi*wi; zi = zr*wi + zi*wr; zr = tt;
        }
    }
    __syncthreads();
    {
        float s = 0.f;
        for (int q = 0; q < 64; ++q) s += smre[n][q];
        kv[n] = s;
    }
    __syncthreads();
    float dc = D[c];
    for (int j = 0; j < 64; ++j) {
        float val = (n >= j) ? kv[n - j] : 0.f;
        if (n == j) val += dc;
        GT[(128 + j)*64 + n] = tf32rna(val);
    }
}

// ---------------- v = x + posenc, transposed store [bc][j][k] ----------------
__global__ void v_kernel(const float* __restrict__ x) {
    int i4 = blockIdx.x * blockDim.x + threadIdx.x;
    if (i4 >= BC*Lt/4) return;
    int l4 = i4 & (Lt/4 - 1);
    int bc = i4 >> 10;
    int c  = bc & (Hc - 1);
    int l  = l4 << 2;
    int lw = l & 15, lh = (l >> 4) & 15, lf = l >> 8;
    float4 xv = ((const float4*)x)[i4];
    float4 pv;
    if (c < CH3) {
        float e = g_emb[lf*CH3 + c];
        pv = make_float4(e, e, e, e);
    } else if (c < 2*CH3) {
        float e = g_emb[(16 + lh)*CH3 + (c - CH3)];
        pv = make_float4(e, e, e, e);
    } else {
        int k = c - 2*CH3;
        const float* ez = g_emb + 32*CH3 + k;
        pv = make_float4(ez[(lw+0)*CH3], ez[(lw+1)*CH3], ez[(lw+2)*CH3], ez[(lw+3)*CH3]);
    }
    int kk = l >> 6, j = l & 63;
    float* dst = g_vt + (size_t)bc * Lt + (size_t)j * 64 + kk;
    dst[0]   = tf32rna(xv.x + pv.x);
    dst[64]  = tf32rna(xv.y + pv.y);
    dst[128] = tf32rna(xv.z + pv.z);
    dst[192] = tf32rna(xv.w + pv.w);
}

// ---------------- fused SSM: B=Qt@V -> in-smem scan -> Y=[G|T]@[S0;V] -> gelu ----------------
// one CTA per (b,c); 128 threads = 4 warps; dynamic smem: Vs 64x68, Bs 128x68, As 64x68
#define SP 68
#define SMEMSZ ((64*SP + 128*SP + 64*SP)*4)

__global__ __launch_bounds__(128) void fused_kernel() {
    extern __shared__ float sm[];
    float* Vs = sm;                    // [64][SP]   V [j][k]
    float* Bs = sm + 64*SP;            // [128][SP]  B, then S0 [row][k]
    float* As = sm + 64*SP + 128*SP;   // [64][SP]   A-operand stage

    int bc = blockIdx.x;
    int c  = bc & (Hc - 1);
    int t  = threadIdx.x;
    int lane = t & 31, wrp = t >> 5;
    int gID = lane >> 2, tig = lane & 3;
    int om = wrp << 4;                 // 16 M-rows per warp

    const float* vt = g_vt + (size_t)bc * Lt;
    const float* Qt = g_Qt + (size_t)c * 64*128;
    const float* GT = g_GT + (size_t)c * 192*64;

    // load V (64x64)
    #pragma unroll
    for (int p = 0; p < 8; ++p) {
        int idx = (t + p*128) * 4;
        int r = idx >> 6, col = idx & 63;
        *(float4*)&Vs[r*SP + col] = *(const float4*)&vt[idx];
    }

    // ---- pass A: B[n][k] = sum_j Qt[j][n] * V[j][k], two 64-row m-halves ----
    #pragma unroll
    for (int mh = 0; mh < 2; ++mh) {
        __syncthreads();
        #pragma unroll
        for (int p = 0; p < 8; ++p) {
            int idx = (t + p*128) * 4;
            int j = idx >> 6, col = idx & 63;
            *(float4*)&As[j*SP + col] = *(const float4*)&Qt[j*128 + mh*64 + col];
        }
        __syncthreads();
        float acc[8][4];
        #pragma unroll
        for (int nt = 0; nt < 8; ++nt)
            #pragma unroll
            for (int r = 0; r < 4; ++r) acc[nt][r] = 0.f;
        #pragma unroll
        for (int k8 = 0; k8 < 8; ++k8) {
            int kd = k8 << 3;
            int r0 = om + gID;
            uint32_t a0 = __float_as_uint(As[(kd + tig    )*SP + r0]);
            uint32_t a1 = __float_as_uint(As[(kd + tig    )*SP + r0 + 8]);
            uint32_t a2 = __float_as_uint(As[(kd + tig + 4)*SP + r0]);
            uint32_t a3 = __float_as_uint(As[(kd + tig + 4)*SP + r0 + 8]);
            #pragma unroll
            for (int nt = 0; nt < 8; ++nt) {
                int cn = (nt << 3) + gID;
                uint32_t b0 = __float_as_uint(Vs[(kd + tig    )*SP + cn]);
                uint32_t b1 = __float_as_uint(Vs[(kd + tig + 4)*SP + cn]);
                asm("mma.sync.aligned.m16n8k8.row.col.f32.tf32.tf32.f32 "
                    "{%0,%1,%2,%3},{%4,%5,%6,%7},{%8,%9},{%0,%1,%2,%3};"
                    : "+f"(acc[nt][0]), "+f"(acc[nt][1]),
                      "+f"(acc[nt][2]), "+f"(acc[nt][3])
                    : "r"(a0), "r"(a1), "r"(a2), "r"(a3), "r"(b0), "r"(b1));
            }
        }
        int row0 = mh*64 + om + gID;
        #pragma unroll
        for (int nt = 0; nt < 8; ++nt) {
            int col = (nt << 3) + (tig << 1);
            Bs[row0*SP + col]       = acc[nt][0];
            Bs[row0*SP + col + 1]   = acc[nt][1];
            Bs[(row0+8)*SP + col]     = acc[nt][2];
            Bs[(row0+8)*SP + col + 1] = acc[nt][3];
        }
    }
    __syncthreads();

    // ---- in-smem scan over 64 chunks: S0(k+1) = w^64*S0(k) + B(k); Bs := S0 (tf32) ----
    if (t < 64) {
        int nn = c*64 + t;
        float wr = g_wTre[nn], wi = g_wTim[nn];
        float* rr = &Bs[(2*t)*SP];
        float* ri = &Bs[(2*t + 1)*SP];
        float sr = 0.f, si = 0.f;
        #pragma unroll 8
        for (int k = 0; k < 64; ++k) {
            float br = rr[k], bi = ri[k];
            rr[k] = tf32rna(sr); ri[k] = tf32rna(si);
            float nr = fmaf(wr, sr, fmaf(-wi, si, br));
            si       = fmaf(wr, si, fmaf( wi, sr, bi));
            sr = nr;
        }
    }

    // ---- pass C: Y[t][k] = sum_r GT[r][t] * X[r][k], X = [S0(128) ; V(64)] ----
    float accC[8][4];
    #pragma unroll
    for (int nt = 0; nt < 8; ++nt)
        #pragma unroll
        for (int r = 0; r < 4; ++r) accC[nt][r] = 0.f;

    #pragma unroll
    for (int s = 0; s < 3; ++s) {
        __syncthreads();
        #pragma unroll
        for (int p = 0; p < 8; ++p) {
            int idx = (t + p*128) * 4;
            int r = idx >> 6, col = idx & 63;
            *(float4*)&As[r*SP + col] = *(const float4*)&GT[s*64*64 + idx];
        }
        __syncthreads();
        const float* Bsrc = (s < 2) ? &Bs[s*64*SP] : Vs;
        #pragma unroll
        for (int k8 = 0; k8 < 8; ++k8) {
            int kd = k8 << 3;
            int r0 = om + gID;
            uint32_t a0 = __float_as_uint(As[(kd + tig    )*SP + r0]);
            uint32_t a1 = __float_as_uint(As[(kd + tig    )*SP + r0 + 8]);
            uint32_t a2 = __float_as_uint(As[(kd + tig + 4)*SP + r0]);
            uint32_t a3 = __float_as_uint(As[(kd + tig + 4)*SP + r0 + 8]);
            #pragma unroll
            for (int nt = 0; nt < 8; ++nt) {
                int cn = (nt << 3) + gID;
                uint32_t b0 = __float_as_uint(Bsrc[(kd + tig    )*SP + cn]);
                uint32_t b1 = __float_as_uint(Bsrc[(kd + tig + 4)*SP + cn]);
                asm("mma.sync.aligned.m16n8k8.row.col.f32.tf32.tf32.f32 "
                    "{%0,%1,%2,%3},{%4,%5,%6,%7},{%8,%9},{%0,%1,%2,%3};"
                    : "+f"(accC[nt][0]), "+f"(accC[nt][1]),
                      "+f"(accC[nt][2]), "+f"(accC[nt][3])
                    : "r"(a0), "r"(a1), "r"(a2), "r"(a3), "r"(b0), "r"(b1));
            }
        }
    }

    // ---- epilogue: l = k*64 + t, gelu, tf32 round ----
    float* yp = g_yT + (size_t)bc * Lt;
    int t0 = om + gID;
    #pragma unroll
    for (int nt = 0; nt < 8; ++nt) {
        int k0 = (nt << 3) + (tig << 1);
        yp[(size_t)k0    *64 + t0    ] = tf32rna(gelu_f(accC[nt][0]));
        yp[(size_t)(k0+1)*64 + t0    ] = tf32rna(gelu_f(accC[nt][1]));
        yp[(size_t)k0    *64 + t0 + 8] = tf32rna(gelu_f(accC[nt][2]));
        yp[(size_t)(k0+1)*64 + t0 + 8] = tf32rna(gelu_f(accC[nt][3]));
    }
}

// ---------------- final tf32 GEMM: out = Wt^T @ yT + bias (R8-validated) ----------------
__global__ __launch_bounds__(256) void gemm_kernel(const float* __restrict__ bias,
                                                   float* __restrict__ out) {
    __shared__ float Ws[2][16][132];
    __shared__ float Ys[2][16][132];
    int b  = blockIdx.z;
    int oo = blockIdx.y << 7;
    int ll = blockIdx.x << 7;
    int t  = threadIdx.x;
    int lane = t & 31, wid = t >> 5;
    int om = (wid & 3) << 5;
    int on = (wid >> 2) << 6;
    int gID = lane >> 2, tig = lane & 3;

    int lr = t >> 4;
    int lc = (t & 15) << 2;
    const float* Wp = g_Wt + (size_t)lr * OUTc + oo + lc;
    const float* Yp = g_yT + ((size_t)b * Hc + lr) * Lt + ll + lc;

    float4 wv0 = *(const float4*)Wp;
    float4 wv1 = *(const float4*)(Wp + 64);
    float4 yv0 = *(const float4*)Yp;
    float4 yv1 = *(const float4*)(Yp + 64);

    float acc[2][8][4];
    #pragma unroll
    for (int mt = 0; mt < 2; ++mt)
        #pragma unroll
        for (int nt = 0; nt < 8; ++nt)
            #pragma unroll
            for (int r = 0; r < 4; ++r) acc[mt][nt][r] = 0.f;

    int buf = 0;
    for (int s = 0; s < Hc/16; ++s) {
        *(float4*)&Ws[buf][lr][lc]      = wv0;
        *(float4*)&Ws[buf][lr][lc + 64] = wv1;
        *(float4*)&Ys[buf][lr][lc]      = yv0;
        *(float4*)&Ys[buf][lr][lc + 64] = yv1;
        __syncthreads();
        if (s + 1 < Hc/16) {
            size_t ko = (size_t)(s + 1) * 16;
            wv0 = *(const float4*)(Wp + ko * OUTc);
            wv1 = *(const float4*)(Wp + ko * OUTc + 64);
            yv0 = *(const float4*)(Yp + ko * Lt);
            yv1 = *(const float4*)(Yp + ko * Lt + 64);
        }
        #pragma unroll
        for (int k8 = 0; k8 < 16; k8 += 8) {
            uint32_t a[2][4];
            #pragma unroll
            for (int mt = 0; mt < 2; ++mt) {
                int r0 = om + (mt << 4) + gID;
                a[mt][0] = __float_as_uint(Ws[buf][k8 + tig    ][r0]);
                a[mt][1] = __float_as_uint(Ws[buf][k8 + tig    ][r0 + 8]);
                a[mt][2] = __float_as_uint(Ws[buf][k8 + tig + 4][r0]);
                a[mt][3] = __float_as_uint(Ws[buf][k8 + tig + 4][r0 + 8]);
            }
            uint32_t bf[8][2];
            #pragma unroll
            for (int nt = 0; nt < 8; ++nt) {
                int cn = on + (nt << 3) + gID;
                bf[nt][0] = __float_as_uint(Ys[buf][k8 + tig    ][cn]);
                bf[nt][1] = __float_as_uint(Ys[buf][k8 + tig + 4][cn]);
            }
            #pragma unroll
            for (int mt = 0; mt < 2; ++mt)
                #pragma unroll
                for (int nt = 0; nt < 8; ++nt) {
                    asm("mma.sync.aligned.m16n8k8.row.col.f32.tf32.tf32.f32 "
                        "{%0,%1,%2,%3},{%4,%5,%6,%7},{%8,%9},{%0,%1,%2,%3};"
                        : "+f"(acc[mt][nt][0]), "+f"(acc[mt][nt][1]),
                          "+f"(acc[mt][nt][2]), "+f"(acc[mt][nt][3])
                        : "r"(a[mt][0]), "r"(a[mt][1]), "r"(a[mt][2]), "r"(a[mt][3]),
                          "r"(bf[nt][0]), "r"(bf[nt][1]));
                }
        }
        buf ^= 1;
    }

    #pragma unroll
    for (int mt = 0; mt < 2; ++mt) {
        int o0 = oo + om + (mt << 4) + gID;
        float b0 = __ldg(&bias[o0]);
        float b8 = __ldg(&bias[o0 + 8]);
        float* r0p = out + ((size_t)b * OUTc + o0)     * Lt + ll + on + (tig << 1);
        float* r8p = out + ((size_t)b * OUTc + o0 + 8) * Lt + ll + on + (tig << 1);
        #pragma unroll
        for (int nt = 0; nt < 8; ++nt) {
            *(float2*)(r0p + (nt << 3)) = make_float2(acc[mt][nt][0] + b0, acc[mt][nt][1] + b0);
            *(float2*)(r8p + (nt << 3)) = make_float2(acc[mt][nt][2] + b8, acc[mt][nt][3] + b8);
        }
    }
}

// ---------------- launch ----------------
extern "C" void kernel_launch(void* const* d_in, const int* in_sizes, int n_in,
                              void* d_out, int out_size) {
    const float* x      = (const float*)d_in[0];
    const float* log_dt = (const float*)d_in[1];
    const float* A_re   = (const float*)d_in[2];
    const float* A_im   = (const float*)d_in[3];
    const float* C_re   = (const float*)d_in[4];
    const float* C_im   = (const float*)d_in[5];
    const float* D      = (const float*)d_in[6];
    const float* W      = (const float*)d_in[7];
    const float* bias   = (const float*)d_in[8];
    float* out = (float*)d_out;

    cudaFuncSetAttribute(fused_kernel, cudaFuncAttributeMaxDynamicSharedMemorySize, SMEMSZ);

    prep_emb_kernel<<<(3*16*CH3 + 255)/256, 256>>>();
    prep_ct_kernel<<<(Hc*Nst + 255)/256, 256>>>(log_dt, A_re, A_im, C_re, C_im);
    prep_wt_kernel<<<(Hc*OUTc/4 + 255)/256, 256>>>(W);
    build_kernel<<<Hc, 64>>>(D);
    v_kernel<<<(BC*Lt/4 + 255)/256, 256>>>(x);
    fused_kernel<<<BC, 128, SMEMSZ>>>();
    gemm_kernel<<<dim3(Lt/128, OUTc/128, BSz), 256>>>(bias, out);
}

// round 11
// speedup vs baseline: 1.6889x; 1.0179x over previous
#include <cuda_runtime.h>
#include <math.h>
#include <stdint.h>

#define Hc   1024
#define Nst  64
#define Lt   4096
#define OUTc 512
#define BSz  2
#define BC   (BSz*Hc)
#define CH3  342   // per-axis posenc channels

// ---------------- helpers ----------------
__device__ __forceinline__ float tf32rna(float v) {
    uint32_t u; asm("cvt.rna.tf32.f32 %0, %1;" : "=r"(u) : "f"(v));
    return __uint_as_float(u);
}
__device__ __forceinline__ float gelu_f(float s) {
    float a2 = 1.5957691216057308f * fmaf(0.044715f * s, s * s, s);
    float e  = __expf(a2);
    float th = 1.0f - __fdividef(2.0f, e + 1.0f);
    return 0.5f * s * (1.0f + th);
}

// ---------------- scratch ----------------
__device__ float g_yT[BC*Lt];        // gelu output, (b, c, l), tf32
__device__ float g_Wt[Hc*OUTc];      // W tf32
__device__ float g_Qt[Hc*64*128];    // [c][j][n]  pass-A A-operand (tf32)
__device__ float g_GT[Hc*192*64];    // [c][r][t]  pass-C A-operand (tf32)
__device__ float g_wre[Hc*Nst],  g_wim[Hc*Nst];
__device__ float g_wTre[Hc*Nst], g_wTim[Hc*Nst];   // w^64
__device__ float g_ctre[Hc*Nst], g_ctim[Hc*Nst];
__device__ float g_emb[3*16*CH3];

// ---------------- merged prep: Wt-round | discretize | emb ----------------
#define NWT (Hc*OUTc/4)
#define NCT (Hc*Nst)
#define NEMB (3*16*CH3)

__global__ void prep_all_kernel(const float* __restrict__ W,
                                const float* __restrict__ log_dt,
                                const float* __restrict__ Are, const float* __restrict__ Aim,
                                const float* __restrict__ Cre, const float* __restrict__ Cim) {
    int idx = blockIdx.x * blockDim.x + threadIdx.x;
    if (idx < NWT) {
        float4 w = ((const float4*)W)[idx];
        ((float4*)g_Wt)[idx] = make_float4(tf32rna(w.x), tf32rna(w.y), tf32rna(w.z), tf32rna(w.w));
        return;
    }
    int i2 = idx - NWT;
    if (i2 < NCT) {
        int c = i2 >> 6;
        double dt  = exp((double)log_dt[c]);
        double ar  = (double)Are[i2], ai = (double)Aim[i2];
        double dar = dt*ar, dai = dt*ai;
        double er  = exp(dar);
        double wr = er*cos(dai), wi = er*sin(dai);
        g_wre[i2] = (float)wr; g_wim[i2] = (float)wi;
        double erT = exp(64.0 * dar);
        g_wTre[i2] = (float)(erT*cos(64.0*dai));
        g_wTim[i2] = (float)(erT*sin(64.0*dai));
        double nr = wr - 1.0, ni = wi;
        double inv = 1.0 / (ar*ar + ai*ai);
        double qr = (nr*ar + ni*ai) * inv;
        double qi = (ni*ar - nr*ai) * inv;
        double cr = (double)Cre[i2], ci = (double)Cim[i2];
        g_ctre[i2] = (float)(2.0*(cr*qr - ci*qi));
        g_ctim[i2] = (float)(2.0*(cr*qi + ci*qr));
        return;
    }
    int i3 = i2 - NCT;
    if (i3 < NEMB) {
        int k   = i3 % CH3;
        int pos = (i3 / CH3) % 16;
        int i   = k >> 1;
        float freq = expf(-logf(10000.0f) * (float)(2*i) / (float)CH3);
        float arg  = (float)pos * freq;
        g_emb[i3] = (k & 1) ? cosf(arg) : sinf(arg);
    }
}

// ---------------- build Qt / GT (+ Toeplitz with D on diagonal) per channel ----------------
__global__ __launch_bounds__(64) void build_kernel(const float* __restrict__ D) {
    __shared__ float smre[64][65];
    __shared__ float smim[64][65];
    __shared__ float kv[64];
    int c = blockIdx.x;
    int n = threadIdx.x;
    int nn = c*64 + n;
    float wr = g_wre[nn], wi = g_wim[nn];
    float cr = g_ctre[nn], ci = g_ctim[nn];
    float* Qt = g_Qt + (size_t)c * 64*128;
    float* GT = g_GT + (size_t)c * 192*64;

    // powers w^0..w^63 -> Qt[j][2n]=Re(w^{63-j}), [2n+1]=Im
    {
        float pr = 1.f, pi = 0.f;
        for (int d = 0; d < 64; ++d) {
            smre[d][n] = pr; smim[d][n] = pi;
            float t = pr*wr - pi*wi; pi = pr*wi + pi*wr; pr = t;
        }
    }
    __syncthreads();
    for (int j = 0; j < 64; ++j) {
        float2 q = make_float2(tf32rna(smre[63-j][n]), tf32rna(smim[63-j][n]));
        *(float2*)&Qt[j*128 + 2*n] = q;
    }
    __syncthreads();
    // z = Ct*w^{t+1} -> GT[2n][t]=Re z, GT[2n+1][t]=-Im z
    {
        float zr = cr*wr - ci*wi, zi = cr*wi + ci*wr;
        for (int t = 0; t < 64; ++t) {
            smre[t][n] = zr; smim[t][n] = -zi;
            float tt = zr*wr - zi*wi; zi = zr*wi + zi*wr; zr = tt;
        }
    }
    __syncthreads();
    for (int r = 0; r < 128; ++r) {
        int sn = r >> 1;
        GT[r*64 + n] = tf32rna((r & 1) ? smim[n][sn] : smre[n][sn]);
    }
    __syncthreads();
    // K[d] = Re(sum_n Ct*w^d); Toeplitz rows 128+j: K[t-j], diag += D
    {
        float zr = cr, zi = ci;
        for (int d = 0; d < 64; ++d) {
            smre[d][n] = zr;
            float tt = zr*wr - zi*wi; zi = zr*wi + zi*wr; zr = tt;
        }
    }
    __syncthreads();
    {
        float s = 0.f;
        for (int q = 0; q < 64; ++q) s += smre[n][q];
        kv[n] = s;
    }
    __syncthreads();
    float dc = D[c];
    for (int j = 0; j < 64; ++j) {
        float val = (n >= j) ? kv[n - j] : 0.f;
        if (n == j) val += dc;
        GT[(128 + j)*64 + n] = tf32rna(val);
    }
}

// ---------------- fused SSM: v=x+pe (in-smem transpose) -> B=Qt@V -> scan -> Y=[G|T]@[S0;V] -> gelu ----------------
// one CTA per (b,c); 128 threads = 4 warps; dynamic smem: Vs 64x68, Bs 128x68, As 64x68
#define SP 68
#define SMEMSZ ((64*SP + 128*SP + 64*SP)*4)

__global__ __launch_bounds__(128) void fused_kernel(const float* __restrict__ xin) {
    extern __shared__ float sm[];
    float* Vs = sm;                    // [64][SP]   V [j][k]
    float* Bs = sm + 64*SP;            // [128][SP]  B, then S0 [row][k]
    float* As = sm + 64*SP + 128*SP;   // [64][SP]   A-operand stage

    int bc = blockIdx.x;
    int c  = bc & (Hc - 1);
    int t  = threadIdx.x;
    int lane = t & 31, wrp = t >> 5;
    int gID = lane >> 2, tig = lane & 3;
    int om = wrp << 4;                 // 16 M-rows per warp

    const float* Qt = g_Qt + (size_t)c * 64*128;
    const float* GT = g_GT + (size_t)c * 192*64;

    // ---- v = x + posenc, transposed into Vs[j][k] ----
    {
        int cax; const float* et;
        if (c < CH3)        { cax = 0; et = g_emb + c; }
        else if (c < 2*CH3) { cax = 1; et = g_emb + 16*CH3 + (c - CH3); }
        else                { cax = 2; et = g_emb + 32*CH3 + (c - 2*CH3); }
        const float* xp = xin + (size_t)bc * Lt;
        #pragma unroll
        for (int p = 0; p < 8; ++p) {
            int l = (t + p*128) << 2;
            float4 xv = *(const float4*)&xp[l];
            float p0, p1, p2, p3;
            if (cax == 0)      { float e = et[(l >> 8)*CH3];        p0 = p1 = p2 = p3 = e; }
            else if (cax == 1) { float e = et[((l >> 4) & 15)*CH3]; p0 = p1 = p2 = p3 = e; }
            else {
                int lw = l & 15;
                p0 = et[lw*CH3]; p1 = et[(lw+1)*CH3]; p2 = et[(lw+2)*CH3]; p3 = et[(lw+3)*CH3];
            }
            int j = l & 63, k = l >> 6;
            Vs[(j  )*SP + k] = tf32rna(xv.x + p0);
            Vs[(j+1)*SP + k] = tf32rna(xv.y + p1);
            Vs[(j+2)*SP + k] = tf32rna(xv.z + p2);
            Vs[(j+3)*SP + k] = tf32rna(xv.w + p3);
        }
    }

    // ---- pass A: B[n][k] = sum_j Qt[j][n] * V[j][k], two 64-row m-halves ----
    #pragma unroll
    for (int mh = 0; mh < 2; ++mh) {
        __syncthreads();
        #pragma unroll
        for (int p = 0; p < 8; ++p) {
            int idx = (t + p*128) * 4;
            int j = idx >> 6, col = idx & 63;
            *(float4*)&As[j*SP + col] = *(const float4*)&Qt[j*128 + mh*64 + col];
        }
        __syncthreads();
        float acc[8][4];
        #pragma unroll
        for (int nt = 0; nt < 8; ++nt)
            #pragma unroll
            for (int r = 0; r < 4; ++r) acc[nt][r] = 0.f;
        #pragma unroll
        for (int k8 = 0; k8 < 8; ++k8) {
            int kd = k8 << 3;
            int r0 = om + gID;
            uint32_t a0 = __float_as_uint(As[(kd + tig    )*SP + r0]);
            uint32_t a1 = __float_as_uint(As[(kd + tig    )*SP + r0 + 8]);
            uint32_t a2 = __float_as_uint(As[(kd + tig + 4)*SP + r0]);
            uint32_t a3 = __float_as_uint(As[(kd + tig + 4)*SP + r0 + 8]);
            #pragma unroll
            for (int nt = 0; nt < 8; ++nt) {
                int cn = (nt << 3) + gID;
                uint32_t b0 = __float_as_uint(Vs[(kd + tig    )*SP + cn]);
                uint32_t b1 = __float_as_uint(Vs[(kd + tig + 4)*SP + cn]);
                asm("mma.sync.aligned.m16n8k8.row.col.f32.tf32.tf32.f32 "
                    "{%0,%1,%2,%3},{%4,%5,%6,%7},{%8,%9},{%0,%1,%2,%3};"
                    : "+f"(acc[nt][0]), "+f"(acc[nt][1]),
                      "+f"(acc[nt][2]), "+f"(acc[nt][3])
                    : "r"(a0), "r"(a1), "r"(a2), "r"(a3), "r"(b0), "r"(b1));
            }
        }
        int row0 = mh*64 + om + gID;
        #pragma unroll
        for (int nt = 0; nt < 8; ++nt) {
            int col = (nt << 3) + (tig << 1);
            Bs[row0*SP + col]         = acc[nt][0];
            Bs[row0*SP + col + 1]     = acc[nt][1];
            Bs[(row0+8)*SP + col]     = acc[nt][2];
            Bs[(row0+8)*SP + col + 1] = acc[nt][3];
        }
    }
    __syncthreads();

    // ---- in-smem scan over 64 chunks: S0(k+1) = w^64*S0(k) + B(k); Bs := S0 (tf32) ----
    if (t < 64) {
        int nn = c*64 + t;
        float wr = g_wTre[nn], wi = g_wTim[nn];
        float* rr = &Bs[(2*t)*SP];
        float* ri = &Bs[(2*t + 1)*SP];
        float sr = 0.f, si = 0.f;
        #pragma unroll 8
        for (int k = 0; k < 64; ++k) {
            float br = rr[k], bi = ri[k];
            rr[k] = tf32rna(sr); ri[k] = tf32rna(si);
            float nr = fmaf(wr, sr, fmaf(-wi, si, br));
            si       = fmaf(wr, si, fmaf( wi, sr, bi));
            sr = nr;
        }
    }

    // ---- pass C: Y[t][k] = sum_r GT[r][t] * X[r][k], X = [S0(128) ; V(64)] ----
    float accC[8][4];
    #pragma unroll
    for (int nt = 0; nt < 8; ++nt)
        #pragma unroll
        for (int r = 0; r < 4; ++r) accC[nt][r] = 0.f;

    #pragma unroll
    for (int s = 0; s < 3; ++s) {
        __syncthreads();
        #pragma unroll
        for (int p = 0; p < 8; ++p) {
            int idx = (t + p*128) * 4;
            int r = idx >> 6, col = idx & 63;
            *(float4*)&As[r*SP + col] = *(const float4*)&GT[s*64*64 + idx];
        }
        __syncthreads();
        const float* Bsrc = (s < 2) ? &Bs[s*64*SP] : Vs;
        #pragma unroll
        for (int k8 = 0; k8 < 8; ++k8) {
            int kd = k8 << 3;
            int r0 = om + gID;
            uint32_t a0 = __float_as_uint(As[(kd + tig    )*SP + r0]);
            uint32_t a1 = __float_as_uint(As[(kd + tig    )*SP + r0 + 8]);
            uint32_t a2 = __float_as_uint(As[(kd + tig + 4)*SP + r0]);
            uint32_t a3 = __float_as_uint(As[(kd + tig + 4)*SP + r0 + 8]);
            #pragma unroll
            for (int nt = 0; nt < 8; ++nt) {
                int cn = (nt << 3) + gID;
                uint32_t b0 = __float_as_uint(Bsrc[(kd + tig    )*SP + cn]);
                uint32_t b1 = __float_as_uint(Bsrc[(kd + tig + 4)*SP + cn]);
                asm("mma.sync.aligned.m16n8k8.row.col.f32.tf32.tf32.f32 "
                    "{%0,%1,%2,%3},{%4,%5,%6,%7},{%8,%9},{%0,%1,%2,%3};"
                    : "+f"(accC[nt][0]), "+f"(accC[nt][1]),
                      "+f"(accC[nt][2]), "+f"(accC[nt][3])
                    : "r"(a0), "r"(a1), "r"(a2), "r"(a3), "r"(b0), "r"(b1));
            }
        }
    }

    // ---- epilogue: l = k*64 + t, gelu, tf32 round ----
    float* yp = g_yT + (size_t)bc * Lt;
    int t0 = om + gID;
    #pragma unroll
    for (int nt = 0; nt < 8; ++nt) {
        int k0 = (nt << 3) + (tig << 1);
        yp[(size_t)k0    *64 + t0    ] = tf32rna(gelu_f(accC[nt][0]));
        yp[(size_t)(k0+1)*64 + t0    ] = tf32rna(gelu_f(accC[nt][1]));
        yp[(size_t)k0    *64 + t0 + 8] = tf32rna(gelu_f(accC[nt][2]));
        yp[(size_t)(k0+1)*64 + t0 + 8] = tf32rna(gelu_f(accC[nt][3]));
    }
}

// ---------------- final tf32 GEMM: out = Wt^T @ yT + bias (R8-validated) ----------------
__global__ __launch_bounds__(256) void gemm_kernel(const float* __restrict__ bias,
                                                   float* __restrict__ out) {
    __shared__ float Ws[2][16][132];
    __shared__ float Ys[2][16][132];
    int b  = blockIdx.z;
    int oo = blockIdx.y << 7;
    int ll = blockIdx.x << 7;
    int t  = threadIdx.x;
    int lane = t & 31, wid = t >> 5;
    int om = (wid & 3) << 5;
    int on = (wid >> 2) << 6;
    int gID = lane >> 2, tig = lane & 3;

    int lr = t >> 4;
    int lc = (t & 15) << 2;
    const float* Wp = g_Wt + (size_t)lr * OUTc + oo + lc;
    const float* Yp = g_yT + ((size_t)b * Hc + lr) * Lt + ll + lc;

    float4 wv0 = *(const float4*)Wp;
    float4 wv1 = *(const float4*)(Wp + 64);
    float4 yv0 = *(const float4*)Yp;
    float4 yv1 = *(const float4*)(Yp + 64);

    float acc[2][8][4];
    #pragma unroll
    for (int mt = 0; mt < 2; ++mt)
        #pragma unroll
        for (int nt = 0; nt < 8; ++nt)
            #pragma unroll
            for (int r = 0; r < 4; ++r) acc[mt][nt][r] = 0.f;

    int buf = 0;
    for (int s = 0; s < Hc/16; ++s) {
        *(float4*)&Ws[buf][lr][lc]      = wv0;
        *(float4*)&Ws[buf][lr][lc + 64] = wv1;
        *(float4*)&Ys[buf][lr][lc]      = yv0;
        *(float4*)&Ys[buf][lr][lc + 64] = yv1;
        __syncthreads();
        if (s + 1 < Hc/16) {
            size_t ko = (size_t)(s + 1) * 16;
            wv0 = *(const float4*)(Wp + ko * OUTc);
            wv1 = *(const float4*)(Wp + ko * OUTc + 64);
            yv0 = *(const float4*)(Yp + ko * Lt);
            yv1 = *(const float4*)(Yp + ko * Lt + 64);
        }
        #pragma unroll
        for (int k8 = 0; k8 < 16; k8 += 8) {
            uint32_t a[2][4];
            #pragma unroll
            for (int mt = 0; mt < 2; ++mt) {
                int r0 = om + (mt << 4) + gID;
                a[mt][0] = __float_as_uint(Ws[buf][k8 + tig    ][r0]);
                a[mt][1] = __float_as_uint(Ws[buf][k8 + tig    ][r0 + 8]);
                a[mt][2] = __float_as_uint(Ws[buf][k8 + tig + 4][r0]);
                a[mt][3] = __float_as_uint(Ws[buf][k8 + tig + 4][r0 + 8]);
            }
            uint32_t bf[8][2];
            #pragma unroll
            for (int nt = 0; nt < 8; ++nt) {
                int cn = on + (nt << 3) + gID;
                bf[nt][0] = __float_as_uint(Ys[buf][k8 + tig    ][cn]);
                bf[nt][1] = __float_as_uint(Ys[buf][k8 + tig + 4][cn]);
            }
            #pragma unroll
            for (int mt = 0; mt < 2; ++mt)
                #pragma unroll
                for (int nt = 0; nt < 8; ++nt) {
                    asm("mma.sync.aligned.m16n8k8.row.col.f32.tf32.tf32.f32 "
                        "{%0,%1,%2,%3},{%4,%5,%6,%7},{%8,%9},{%0,%1,%2,%3};"
                        : "+f"(acc[mt][nt][0]), "+f"(acc[mt][nt][1]),
                          "+f"(acc[mt][nt][2]), "+f"(acc[mt][nt][3])
                        : "r"(a[mt][0]), "r"(a[mt][1]), "r"(a[mt][2]), "r"(a[mt][3]),
                          "r"(bf[nt][0]), "r"(bf[nt][1]));
                }
        }
        buf ^= 1;
    }

    #pragma unroll
    for (int mt = 0; mt < 2; ++mt) {
        int o0 = oo + om + (mt << 4) + gID;
        float b0 = __ldg(&bias[o0]);
        float b8 = __ldg(&bias[o0 + 8]);
        float* r0p = out + ((size_t)b * OUTc + o0)     * Lt + ll + on + (tig << 1);
        float* r8p = out + ((size_t)b * OUTc + o0 + 8) * Lt + ll + on + (tig << 1);
        #pragma unroll
        for (int nt = 0; nt < 8; ++nt) {
            *(float2*)(r0p + (nt << 3)) = make_float2(acc[mt][nt][0] + b0, acc[mt][nt][1] + b0);
            *(float2*)(r8p + (nt << 3)) = make_float2(acc[mt][nt][2] + b8, acc[mt][nt][3] + b8);
        }
    }
}

// ---------------- launch ----------------
extern "C" void kernel_launch(void* const* d_in, const int* in_sizes, int n_in,
                              void* d_out, int out_size) {
    const float* x      = (const float*)d_in[0];
    const float* log_dt = (const float*)d_in[1];
    const float* A_re   = (const float*)d_in[2];
    const float* A_im   = (const float*)d_in[3];
    const float* C_re   = (const float*)d_in[4];
    const float* C_im   = (const float*)d_in[5];
    const float* D      = (const float*)d_in[6];
    const float* W      = (const float*)d_in[7];
    const float* bias   = (const float*)d_in[8];
    float* out = (float*)d_out;

    cudaFuncSetAttribute(fused_kernel, cudaFuncAttributeMaxDynamicSharedMemorySize, SMEMSZ);

    int nprep = NWT + NCT + NEMB;
    prep_all_kernel<<<(nprep + 255)/256, 256>>>(W, log_dt, A_re, A_im, C_re, C_im);
    build_kernel<<<Hc, 64>>>(D);
    fused_kernel<<<BC, 128, SMEMSZ>>>(x);
    gemm_kernel<<<dim3(Lt/128, OUTc/128, BSz), 256>>>(bias, out);
}

// round 12
// speedup vs baseline: 1.8377x; 1.0881x over previous
#include <cuda_runtime.h>
#include <math.h>
#include <stdint.h>

#define Hc   1024
#define Nst  64
#define Lt   4096
#define OUTc 512
#define BSz  2
#define BC   (BSz*Hc)
#define CH3  342   // per-axis posenc channels

// ---------------- helpers ----------------
__device__ __forceinline__ float tf32rna(float v) {
    uint32_t u; asm("cvt.rna.tf32.f32 %0, %1;" : "=r"(u) : "f"(v));
    return __uint_as_float(u);
}
__device__ __forceinline__ float gelu_f(float s) {
    float a2 = 1.5957691216057308f * fmaf(0.044715f * s, s * s, s);
    float e  = __expf(a2);
    float th = 1.0f - __fdividef(2.0f, e + 1.0f);
    return 0.5f * s * (1.0f + th);
}
#define MMA_TF32(acc, a0,a1,a2,a3, b0,b1) \
    asm("mma.sync.aligned.m16n8k8.row.col.f32.tf32.tf32.f32 " \
        "{%0,%1,%2,%3},{%4,%5,%6,%7},{%8,%9},{%0,%1,%2,%3};" \
        : "+f"(acc[0]), "+f"(acc[1]), "+f"(acc[2]), "+f"(acc[3]) \
        : "r"(a0), "r"(a1), "r"(a2), "r"(a3), "r"(b0), "r"(b1))

// ---------------- scratch ----------------
__device__ float  g_yT[BC*Lt];          // gelu output, (b, c, l), tf32
__device__ float4 g_Wp [128*32*32];     // W fragment-packed: [kb][mb][lane]
__device__ float4 g_QtP[Hc*2048];       // per c: [kb0..7][mb0..7][lane]
__device__ float4 g_GTP[Hc*3072];       // per c: [kb0..23][mb0..3][lane]
__device__ float g_wre[Hc*Nst],  g_wim[Hc*Nst];
__device__ float g_wTre[Hc*Nst], g_wTim[Hc*Nst];   // w^64
__device__ float g_ctre[Hc*Nst], g_ctim[Hc*Nst];
__device__ float g_emb[3*16*CH3];

// ---------------- merged prep: W fragment-pack | discretize | emb ----------------
#define NWP (128*32*32)
#define NCT (Hc*Nst)
#define NEMB (3*16*CH3)

__global__ void prep_all_kernel(const float* __restrict__ W,
                                const float* __restrict__ log_dt,
                                const float* __restrict__ Are, const float* __restrict__ Aim,
                                const float* __restrict__ Cre, const float* __restrict__ Cim) {
    int idx = blockIdx.x * blockDim.x + threadIdx.x;
    if (idx < NWP) {
        int kb = idx >> 10;
        int mb = (idx >> 5) & 31;
        int ln = idx & 31;
        int g = ln >> 2, tg = ln & 3;
        int m0 = mb*16 + g, k0 = kb*8 + tg;
        float4 v;
        v.x = tf32rna(W[(size_t)k0*OUTc + m0]);
        v.y = tf32rna(W[(size_t)k0*OUTc + m0 + 8]);
        v.z = tf32rna(W[(size_t)(k0+4)*OUTc + m0]);
        v.w = tf32rna(W[(size_t)(k0+4)*OUTc + m0 + 8]);
        g_Wp[idx] = v;
        return;
    }
    int i2 = idx - NWP;
    if (i2 < NCT) {
        int c = i2 >> 6;
        double dt  = exp((double)log_dt[c]);
        double ar  = (double)Are[i2], ai = (double)Aim[i2];
        double dar = dt*ar, dai = dt*ai;
        double er  = exp(dar);
        double wr = er*cos(dai), wi = er*sin(dai);
        g_wre[i2] = (float)wr; g_wim[i2] = (float)wi;
        double erT = exp(64.0 * dar);
        g_wTre[i2] = (float)(erT*cos(64.0*dai));
        g_wTim[i2] = (float)(erT*sin(64.0*dai));
        double nr = wr - 1.0, ni = wi;
        double inv = 1.0 / (ar*ar + ai*ai);
        double qr = (nr*ar + ni*ai) * inv;
        double qi = (ni*ar - nr*ai) * inv;
        double cr = (double)Cre[i2], ci = (double)Cim[i2];
        g_ctre[i2] = (float)(2.0*(cr*qr - ci*qi));
        g_ctim[i2] = (float)(2.0*(cr*qi + ci*qr));
        return;
    }
    int i3 = i2 - NCT;
    if (i3 < NEMB) {
        int k   = i3 % CH3;
        int pos = (i3 / CH3) % 16;
        int i   = k >> 1;
        float freq = expf(-logf(10000.0f) * (float)(2*i) / (float)CH3);
        float arg  = (float)pos * freq;
        g_emb[i3] = (k & 1) ? cosf(arg) : sinf(arg);
    }
}

// ---------------- build QtP / GTP (fragment-packed) per channel ----------------
__global__ __launch_bounds__(64) void build_kernel(const float* __restrict__ D) {
    __shared__ float smre[64][65];
    __shared__ float smim[64][65];
    __shared__ float kv[64];
    int c = blockIdx.x;
    int n = threadIdx.x;
    int nn = c*64 + n;
    float wr = g_wre[nn], wi = g_wim[nn];
    float cr = g_ctre[nn], ci = g_ctim[nn];
    float4* QtP = g_QtP + (size_t)c * 2048;
    float4* GTP = g_GTP + (size_t)c * 3072;

    // phase 1: powers w^0..w^63 per state n
    {
        float pr = 1.f, pi = 0.f;
        for (int d = 0; d < 64; ++d) {
            smre[d][n] = pr; smim[d][n] = pi;
            float t = pr*wr - pi*wi; pi = pr*wi + pi*wr; pr = t;
        }
    }
    __syncthreads();
    // pack Qt: A[m][k] = (m&1 ? Im : Re)(w^{63-k}) of state m>>1
    for (int p = n; p < 2048; p += 64) {
        int kb = p >> 8, mb = (p >> 5) & 7, ln = p & 31;
        int g = ln >> 2, tg = ln & 3;
        int m0 = mb*16 + g, k0 = kb*8 + tg;
        float4 v;
        #define QV(m,k) tf32rna(((m)&1) ? smim[63-(k)][(m)>>1] : smre[63-(k)][(m)>>1])
        v.x = QV(m0,   k0); v.y = QV(m0+8, k0);
        v.z = QV(m0, k0+4); v.w = QV(m0+8, k0+4);
        #undef QV
        QtP[p] = v;
    }
    __syncthreads();
    // phase 2: z = Ct*w^{t+1}: smre[t][n]=Re, smim[t][n]=-Im
    {
        float zr = cr*wr - ci*wi, zi = cr*wi + ci*wr;
        for (int t = 0; t < 64; ++t) {
            smre[t][n] = zr; smim[t][n] = -zi;
            float tt = zr*wr - zi*wi; zi = zr*wi + zi*wr; zr = tt;
        }
    }
    __syncthreads();
    // pack GT rows r<128: A[m=t][k=r] = (r&1 ? smim : smre)[t][r>>1]
    for (int p = n; p < 2048; p += 64) {
        int kb = p >> 7, mb = (p >> 5) & 3, ln = p & 31;
        int g = ln >> 2, tg = ln & 3;
        int m0 = mb*16 + g, r0 = kb*8 + tg;
        float4 v;
        #define GV(t,r) tf32rna(((r)&1) ? smim[t][(r)>>1] : smre[t][(r)>>1])
        v.x = GV(m0,   r0); v.y = GV(m0+8, r0);
        v.z = GV(m0, r0+4); v.w = GV(m0+8, r0+4);
        #undef GV
        GTP[p] = v;
    }
    __syncthreads();
    // phase 3: K[d] = Re(sum_n Ct*w^d)
    {
        float zr = cr, zi = ci;
        for (int d = 0; d < 64; ++d) {
            smre[d][n] = zr;
            float tt = zr*wr - zi*wi; zi = zr*wi + zi*wr; zr = tt;
        }
    }
    __syncthreads();
    {
        float s = 0.f;
        for (int q = 0; q < 64; ++q) s += smre[n][q];
        kv[n] = s;
    }
    __syncthreads();
    // pack Toeplitz rows r = 128..191: A[t][r] = K[t-j] (j=r-128, t>=j), diag += D
    float dc = D[c];
    for (int p = n; p < 1024; p += 64) {
        int kb = 16 + (p >> 7), mb = (p >> 5) & 3, ln = p & 31;
        int g = ln >> 2, tg = ln & 3;
        int m0 = mb*16 + g, r0 = kb*8 + tg;
        float4 v;
        #define TV(t,r) tf32rna((((t) >= (r)-128) ? kv[(t)-((r)-128)] : 0.f) + (((t) == (r)-128) ? dc : 0.f))
        v.x = TV(m0,   r0); v.y = TV(m0+8, r0);
        v.z = TV(m0, r0+4); v.w = TV(m0+8, r0+4);
        #undef TV
        GTP[2048 + p] = v;
    }
}

// ---------------- fused SSM: v=x+pe -> B=Qt@V -> scan -> Y=[G|T]@[S0;V] -> gelu ----------------
// one CTA per (b,c); 128 threads = 4 warps; dynamic smem: Vs 64x68 + Bs 128x68
#define SP 68
#define SMEMSZ ((64*SP + 128*SP)*4)

__global__ __launch_bounds__(128) void fused_kernel(const float* __restrict__ xin) {
    extern __shared__ float sm[];
    float* Vs = sm;                    // [64][SP]   V [j][k]
    float* Bs = sm + 64*SP;            // [128][SP]  B, then S0 [row][k]

    int bc = blockIdx.x;
    int c  = bc & (Hc - 1);
    int t  = threadIdx.x;
    int lane = t & 31, wrp = t >> 5;
    int gID = lane >> 2, tig = lane & 3;
    int om = wrp << 4;                 // 16 M-rows per warp

    const float4* QtP = g_QtP + (size_t)c * 2048;
    const float4* GTP = g_GTP + (size_t)c * 3072;

    // ---- v = x + posenc, transposed into Vs[j][k] ----
    {
        int cax; const float* et;
        if (c < CH3)        { cax = 0; et = g_emb + c; }
        else if (c < 2*CH3) { cax = 1; et = g_emb + 16*CH3 + (c - CH3); }
        else                { cax = 2; et = g_emb + 32*CH3 + (c - 2*CH3); }
        const float* xp = xin + (size_t)bc * Lt;
        #pragma unroll
        for (int p = 0; p < 8; ++p) {
            int l = (t + p*128) << 2;
            float4 xv = *(const float4*)&xp[l];
            float p0, p1, p2, p3;
            if (cax == 0)      { float e = et[(l >> 8)*CH3];        p0 = p1 = p2 = p3 = e; }
            else if (cax == 1) { float e = et[((l >> 4) & 15)*CH3]; p0 = p1 = p2 = p3 = e; }
            else {
                int lw = l & 15;
                p0 = et[lw*CH3]; p1 = et[(lw+1)*CH3]; p2 = et[(lw+2)*CH3]; p3 = et[(lw+3)*CH3];
            }
            int j = l & 63, k = l >> 6;
            Vs[(j  )*SP + k] = tf32rna(xv.x + p0);
            Vs[(j+1)*SP + k] = tf32rna(xv.y + p1);
            Vs[(j+2)*SP + k] = tf32rna(xv.z + p2);
            Vs[(j+3)*SP + k] = tf32rna(xv.w + p3);
        }
    }
    __syncthreads();

    // ---- pass A: B[n][k] = sum_j Qt[j][n] * V[j][k]; A-frags direct from packed global ----
    #pragma unroll
    for (int mh = 0; mh < 2; ++mh) {
        int Mb = (mh << 2) + wrp;
        float4 qf[8];
        #pragma unroll
        for (int k8 = 0; k8 < 8; ++k8)
            qf[k8] = QtP[(k8*8 + Mb)*32 + lane];
        float acc[8][4];
        #pragma unroll
        for (int nt = 0; nt < 8; ++nt)
            #pragma unroll
            for (int r = 0; r < 4; ++r) acc[nt][r] = 0.f;
        #pragma unroll
        for (int k8 = 0; k8 < 8; ++k8) {
            int kd = k8 << 3;
            uint32_t a0 = __float_as_uint(qf[k8].x), a1 = __float_as_uint(qf[k8].y);
            uint32_t a2 = __float_as_uint(qf[k8].z), a3 = __float_as_uint(qf[k8].w);
            #pragma unroll
            for (int nt = 0; nt < 8; ++nt) {
                int cn = (nt << 3) + gID;
                uint32_t b0 = __float_as_uint(Vs[(kd + tig    )*SP + cn]);
                uint32_t b1 = __float_as_uint(Vs[(kd + tig + 4)*SP + cn]);
                MMA_TF32(acc[nt], a0, a1, a2, a3, b0, b1);
            }
        }
        int row0 = mh*64 + om + gID;
        #pragma unroll
        for (int nt = 0; nt < 8; ++nt) {
            int col = (nt << 3) + (tig << 1);
            Bs[row0*SP + col]         = acc[nt][0];
            Bs[row0*SP + col + 1]     = acc[nt][1];
            Bs[(row0+8)*SP + col]     = acc[nt][2];
            Bs[(row0+8)*SP + col + 1] = acc[nt][3];
        }
    }
    __syncthreads();

    // ---- in-smem scan over 64 chunks: S0(k+1) = w^64*S0(k) + B(k); Bs := S0 (tf32) ----
    if (t < 64) {
        int nn = c*64 + t;
        float wr = g_wTre[nn], wi = g_wTim[nn];
        float* rr = &Bs[(2*t)*SP];
        float* ri = &Bs[(2*t + 1)*SP];
        float sr = 0.f, si = 0.f;
        #pragma unroll 8
        for (int k = 0; k < 64; ++k) {
            float br = rr[k], bi = ri[k];
            rr[k] = tf32rna(sr); ri[k] = tf32rna(si);
            float nr = fmaf(wr, sr, fmaf(-wi, si, br));
            si       = fmaf(wr, si, fmaf( wi, sr, bi));
            sr = nr;
        }
    }
    __syncthreads();

    // ---- pass C: Y[t][k] = sum_r GT[r][t] * X[r][k], X = [S0(128) ; V(64)] ----
    float accC[8][4];
    #pragma unroll
    for (int nt = 0; nt < 8; ++nt)
        #pragma unroll
        for (int r = 0; r < 4; ++r) accC[nt][r] = 0.f;

    #pragma unroll
    for (int s = 0; s < 3; ++s) {
        float4 gf[8];
        #pragma unroll
        for (int k8 = 0; k8 < 8; ++k8)
            gf[k8] = GTP[((s*8 + k8)*4 + wrp)*32 + lane];
        const float* Bsrc = (s < 2) ? &Bs[s*64*SP] : Vs;
        #pragma unroll
        for (int k8 = 0; k8 < 8; ++k8) {
            int kd = k8 << 3;
            uint32_t a0 = __float_as_uint(gf[k8].x), a1 = __float_as_uint(gf[k8].y);
            uint32_t a2 = __float_as_uint(gf[k8].z), a3 = __float_as_uint(gf[k8].w);
            #pragma unroll
            for (int nt = 0; nt < 8; ++nt) {
                int cn = (nt << 3) + gID;
                uint32_t b0 = __float_as_uint(Bsrc[(kd + tig    )*SP + cn]);
                uint32_t b1 = __float_as_uint(Bsrc[(kd + tig + 4)*SP + cn]);
                MMA_TF32(accC[nt], a0, a1, a2, a3, b0, b1);
            }
        }
    }

    // ---- epilogue: l = k*64 + t, gelu, tf32 round ----
    float* yp = g_yT + (size_t)bc * Lt;
    int t0 = om + gID;
    #pragma unroll
    for (int nt = 0; nt < 8; ++nt) {
        int k0 = (nt << 3) + (tig << 1);
        yp[(size_t)k0    *64 + t0    ] = tf32rna(gelu_f(accC[nt][0]));
        yp[(size_t)(k0+1)*64 + t0    ] = tf32rna(gelu_f(accC[nt][1]));
        yp[(size_t)k0    *64 + t0 + 8] = tf32rna(gelu_f(accC[nt][2]));
        yp[(size_t)(k0+1)*64 + t0 + 8] = tf32rna(gelu_f(accC[nt][3]));
    }
}

// ---------------- final tf32 GEMM: out = Wp(frag) @ yT + bias ----------------
// tile 128(o) x 128(l), BK=16, 256 threads = 8 warps (4o x 2l); A-frags via LDG.128
__global__ __launch_bounds__(256, 2) void gemm_kernel(const float* __restrict__ bias,
                                                      float* __restrict__ out) {
    __shared__ float Ys[2][16][132];
    int b  = blockIdx.z;
    int oo = blockIdx.y << 7;
    int ll = blockIdx.x << 7;
    int t  = threadIdx.x;
    int lane = t & 31, wid = t >> 5;
    int om = (wid & 3) << 5;
    int on = (wid >> 2) << 6;
    int gID = lane >> 2, tig = lane & 3;

    int lr = t >> 4;
    int lc = (t & 15) << 2;
    const float* Yp = g_yT + ((size_t)b * Hc + lr) * Lt + ll + lc;
    int MbBase = (oo >> 4) + ((wid & 3) << 1);

    float4 yv0 = *(const float4*)Yp;
    float4 yv1 = *(const float4*)(Yp + 64);

    float4 af[2][2], afn[2][2];
    #pragma unroll
    for (int k8i = 0; k8i < 2; ++k8i)
        #pragma unroll
        for (int mt = 0; mt < 2; ++mt)
            af[k8i][mt] = g_Wp[(size_t)(k8i*32 + MbBase + mt)*32 + lane];

    float acc[2][8][4];
    #pragma unroll
    for (int mt = 0; mt < 2; ++mt)
        #pragma unroll
        for (int nt = 0; nt < 8; ++nt)
            #pragma unroll
            for (int r = 0; r < 4; ++r) acc[mt][nt][r] = 0.f;

    int buf = 0;
    for (int s = 0; s < Hc/16; ++s) {
        *(float4*)&Ys[buf][lr][lc]      = yv0;
        *(float4*)&Ys[buf][lr][lc + 64] = yv1;
        __syncthreads();
        if (s + 1 < Hc/16) {
            size_t ko = (size_t)(s + 1) * 16;
            yv0 = *(const float4*)(Yp + ko * Lt);
            yv1 = *(const float4*)(Yp + ko * Lt + 64);
            #pragma unroll
            for (int k8i = 0; k8i < 2; ++k8i)
                #pragma unroll
                for (int mt = 0; mt < 2; ++mt)
                    afn[k8i][mt] = g_Wp[(size_t)(((s+1)*2 + k8i)*32 + MbBase + mt)*32 + lane];
        }
        #pragma unroll
        for (int k8i = 0; k8i < 2; ++k8i) {
            int k8 = k8i << 3;
            uint32_t bf[8][2];
            #pragma unroll
            for (int nt = 0; nt < 8; ++nt) {
                int cn = on + (nt << 3) + gID;
                bf[nt][0] = __float_as_uint(Ys[buf][k8 + tig    ][cn]);
                bf[nt][1] = __float_as_uint(Ys[buf][k8 + tig + 4][cn]);
            }
            #pragma unroll
            for (int mt = 0; mt < 2; ++mt) {
                uint32_t a0 = __float_as_uint(af[k8i][mt].x), a1 = __float_as_uint(af[k8i][mt].y);
                uint32_t a2 = __float_as_uint(af[k8i][mt].z), a3 = __float_as_uint(af[k8i][mt].w);
                #pragma unroll
                for (int nt = 0; nt < 8; ++nt)
                    MMA_TF32(acc[mt][nt], a0, a1, a2, a3, bf[nt][0], bf[nt][1]);
            }
        }
        #pragma unroll
        for (int k8i = 0; k8i < 2; ++k8i)
            #pragma unroll
            for (int mt = 0; mt < 2; ++mt)
                af[k8i][mt] = afn[k8i][mt];
        buf ^= 1;
        __syncthreads();
    }

    #pragma unroll
    for (int mt = 0; mt < 2; ++mt) {
        int o0 = oo + om + (mt << 4) + gID;
        float b0 = __ldg(&bias[o0]);
        float b8 = __ldg(&bias[o0 + 8]);
        float* r0p = out + ((size_t)b * OUTc + o0)     * Lt + ll + on + (tig << 1);
        float* r8p = out + ((size_t)b * OUTc + o0 + 8) * Lt + ll + on + (tig << 1);
        #pragma unroll
        for (int nt = 0; nt < 8; ++nt) {
            *(float2*)(r0p + (nt << 3)) = make_float2(acc[mt][nt][0] + b0, acc[mt][nt][1] + b0);
            *(float2*)(r8p + (nt << 3)) = make_float2(acc[mt][nt][2] + b8, acc[mt][nt][3] + b8);
        }
    }
}

// ---------------- launch ----------------
extern "C" void kernel_launch(void* const* d_in, const int* in_sizes, int n_in,
                              void* d_out, int out_size) {
    const float* x      = (const float*)d_in[0];
    const float* log_dt = (const float*)d_in[1];
    const float* A_re   = (const float*)d_in[2];
    const float* A_im   = (const float*)d_in[3];
    const float* C_re   = (const float*)d_in[4];
    const float* C_im   = (const float*)d_in[5];
    const float* D      = (const float*)d_in[6];
    const float* W      = (const float*)d_in[7];
    const float* bias   = (const float*)d_in[8];
    float* out = (float*)d_out;

    cudaFuncSetAttribute(fused_kernel, cudaFuncAttributeMaxDynamicSharedMemorySize, SMEMSZ);

    int nprep = NWP + NCT + NEMB;
    prep_all_kernel<<<(nprep + 255)/256, 256>>>(W, log_dt, A_re, A_im, C_re, C_im);
    build_kernel<<<Hc, 64>>>(D);
    fused_kernel<<<BC, 128, SMEMSZ>>>(x);
    gemm_kernel<<<dim3(Lt/128, OUTc/128, BSz), 256>>>(bias, out);
}